// round 1
// baseline (speedup 1.0000x reference)
#include <cuda_runtime.h>
#include <math.h>

// Problem constants
#define Bz 32
#define TE 2048
#define TD 64
#define Dd 1024
#define Mrows (Bz * TE)   // 65536

// Scratch (no allocations allowed -> __device__ globals)
__device__ float g_dU[Bz * Dd];        // dec_last @ U_a : (32, 1024)
__device__ float g_scores[Bz * TE];    // pre-softmax scores
__device__ float g_weights[Bz * TE];   // softmax weights

// ---------------------------------------------------------------------------
// Kernel 0: zero the score accumulator (graph replays must be idempotent)
// ---------------------------------------------------------------------------
__global__ void zero_scores_kernel() {
    int i = blockIdx.x * blockDim.x + threadIdx.x;
    if (i < Bz * TE) g_scores[i] = 0.0f;
}

// ---------------------------------------------------------------------------
// Kernel 1: dec_U[b][f] = sum_e dec_last[b][e] * U[e][f]
// grid (32, 8), block 128 : each thread one f
// ---------------------------------------------------------------------------
__global__ void dU_kernel(const float* __restrict__ dec,
                          const float* __restrict__ U) {
    int b = blockIdx.x;
    int f = blockIdx.y * blockDim.x + threadIdx.x;

    __shared__ float sdec[Dd];
    const float* drow = dec + (size_t)b * TD * Dd + (size_t)(TD - 1) * Dd;
    for (int i = threadIdx.x; i < Dd; i += blockDim.x) sdec[i] = drow[i];
    __syncthreads();

    float acc = 0.0f;
#pragma unroll 8
    for (int e = 0; e < Dd; e++) acc = fmaf(sdec[e], U[(size_t)e * Dd + f], acc);
    g_dU[b * Dd + f] = acc;
}

// ---------------------------------------------------------------------------
// Kernel 2: fused SGEMM + epilogue.
//   C[m][n] = sum_k A[m][k] * W[k][n]   (A = encoder reshaped (65536,1024))
//   scores[m] += sum_{n in tile} V[n] * tanh(C[m][n] + dU[b(m)][n])
// Tiles: BM=128, BN=128, BK=16; 256 threads; 8x8 micro-tile per thread.
// ---------------------------------------------------------------------------
#define BM 128
#define BN 128
#define BK 16

__global__ __launch_bounds__(256, 2)
void gemm_score_kernel(const float* __restrict__ A,
                       const float* __restrict__ W,
                       const float* __restrict__ V) {
    __shared__ float As[BK][BM];   // transposed A tile
    __shared__ float Bs[BK][BN];
    __shared__ float sred[BM];

    const int tid = threadIdx.x;
    const int tm  = tid >> 4;      // 0..15
    const int tn  = tid & 15;      // 0..15
    const int mbase = blockIdx.x * BM;
    const int nbase = blockIdx.y * BN;

    float acc[8][8];
#pragma unroll
    for (int i = 0; i < 8; i++)
#pragma unroll
        for (int j = 0; j < 8; j++) acc[i][j] = 0.0f;

    for (int kt = 0; kt < Dd; kt += BK) {
        // Load A tile (128 rows x 16 k) as float4, store transposed
#pragma unroll
        for (int i = 0; i < 2; i++) {
            int idx = tid * 2 + i;          // 0..511
            int r   = idx >> 2;             // 0..127
            int c4  = idx & 3;              // 0..3
            float4 v = *(const float4*)(A + (size_t)(mbase + r) * Dd + kt + c4 * 4);
            As[c4 * 4 + 0][r] = v.x;
            As[c4 * 4 + 1][r] = v.y;
            As[c4 * 4 + 2][r] = v.z;
            As[c4 * 4 + 3][r] = v.w;
        }
        // Load W tile (16 k x 128 n)
#pragma unroll
        for (int i = 0; i < 2; i++) {
            int idx = tid * 2 + i;          // 0..511
            int r   = idx >> 5;             // 0..15
            int c4  = idx & 31;             // 0..31
            float4 v = *(const float4*)(W + (size_t)(kt + r) * Dd + nbase + c4 * 4);
            *(float4*)&Bs[r][c4 * 4] = v;
        }
        __syncthreads();

#pragma unroll
        for (int kk = 0; kk < BK; kk++) {
            float a[8], bv[8];
            *(float4*)&a[0]  = *(const float4*)&As[kk][tm * 8];
            *(float4*)&a[4]  = *(const float4*)&As[kk][tm * 8 + 4];
            *(float4*)&bv[0] = *(const float4*)&Bs[kk][tn * 8];
            *(float4*)&bv[4] = *(const float4*)&Bs[kk][tn * 8 + 4];
#pragma unroll
            for (int i = 0; i < 8; i++)
#pragma unroll
                for (int j = 0; j < 8; j++)
                    acc[i][j] = fmaf(a[i], bv[j], acc[i][j]);
        }
        __syncthreads();
    }

    // ---- Fused epilogue: partial score = sum_n V[n]*tanh(C + dU) ----
    if (tid < BM) sred[tid] = 0.0f;
    __syncthreads();

    // All 128 rows of this block belong to one batch b (128 divides TE)
    const int b = mbase >> 11;   // mbase / TE
    float dUreg[8], vreg[8];
#pragma unroll
    for (int j = 0; j < 8; j++) {
        dUreg[j] = g_dU[b * Dd + nbase + tn * 8 + j];
        vreg[j]  = V[nbase + tn * 8 + j];
    }
#pragma unroll
    for (int i = 0; i < 8; i++) {
        float s = 0.0f;
#pragma unroll
        for (int j = 0; j < 8; j++)
            s = fmaf(vreg[j], tanhf(acc[i][j] + dUreg[j]), s);
        atomicAdd(&sred[tm * 8 + i], s);
    }
    __syncthreads();

    if (tid < BM) atomicAdd(&g_scores[mbase + tid], sred[tid]);
}

// ---------------------------------------------------------------------------
// Kernel 3: softmax over TE per batch; writes g_weights and d_out weights
// grid 32, block 256 (8 elements per thread)
// ---------------------------------------------------------------------------
__global__ void softmax_kernel(float* __restrict__ out_weights) {
    const int b   = blockIdx.x;
    const int tid = threadIdx.x;
    __shared__ float red[256];

    float local[8];
    float mx = -INFINITY;
#pragma unroll
    for (int i = 0; i < 8; i++) {
        local[i] = g_scores[b * TE + tid + i * 256];
        mx = fmaxf(mx, local[i]);
    }
    red[tid] = mx;
    __syncthreads();
    for (int s = 128; s > 0; s >>= 1) {
        if (tid < s) red[tid] = fmaxf(red[tid], red[tid + s]);
        __syncthreads();
    }
    mx = red[0];
    __syncthreads();

    float sum = 0.0f;
#pragma unroll
    for (int i = 0; i < 8; i++) {
        local[i] = expf(local[i] - mx);
        sum += local[i];
    }
    red[tid] = sum;
    __syncthreads();
    for (int s = 128; s > 0; s >>= 1) {
        if (tid < s) red[tid] += red[tid + s];
        __syncthreads();
    }
    const float inv = 1.0f / red[0];

#pragma unroll
    for (int i = 0; i < 8; i++) {
        float w = local[i] * inv;
        g_weights[b * TE + tid + i * 256]    = w;
        out_weights[b * TE + tid + i * 256]  = w;
    }
}

// ---------------------------------------------------------------------------
// Kernel 4: context[b][e] = sum_t enc[b][t][e] * w[b][t]
// grid (32, 4), block 256 : each thread one e
// ---------------------------------------------------------------------------
__global__ void context_kernel(const float* __restrict__ enc,
                               float* __restrict__ out_context) {
    const int b = blockIdx.x;
    const int e = blockIdx.y * 256 + threadIdx.x;

    __shared__ float sw[TE];
    for (int i = threadIdx.x; i < TE; i += 256) sw[i] = g_weights[b * TE + i];
    __syncthreads();

    const float* base = enc + (size_t)b * TE * Dd + e;
    float acc = 0.0f;
#pragma unroll 8
    for (int t = 0; t < TE; t++)
        acc = fmaf(sw[t], base[(size_t)t * Dd], acc);
    out_context[b * Dd + e] = acc;
}

// ---------------------------------------------------------------------------
// Launch
// Inputs (metadata order): encoder_outputs, decoder_outputs, W_a, U_a, V_a
// Output: context (32*1024 f32) followed by weights (32*2048 f32)
// ---------------------------------------------------------------------------
extern "C" void kernel_launch(void* const* d_in, const int* in_sizes, int n_in,
                              void* d_out, int out_size) {
    const float* enc = (const float*)d_in[0];
    const float* dec = (const float*)d_in[1];
    const float* W_a = (const float*)d_in[2];
    const float* U_a = (const float*)d_in[3];
    const float* V_a = (const float*)d_in[4];
    float* out = (float*)d_out;

    float* out_context = out;               // 32*1024
    float* out_weights = out + Bz * Dd;     // 32*2048

    zero_scores_kernel<<<(Bz * TE + 255) / 256, 256>>>();

    {
        dim3 g(Bz, Dd / 128);
        dU_kernel<<<g, 128>>>(dec, U_a);
    }
    {
        dim3 g(Mrows / BM, Dd / BN);   // (512, 8)
        gemm_score_kernel<<<g, 256>>>(enc, W_a, V_a);
    }
    softmax_kernel<<<Bz, 256>>>(out_weights);
    {
        dim3 g(Bz, Dd / 256);
        context_kernel<<<g, 256>>>(enc, out_context);
    }
}

// round 3
// speedup vs baseline: 2.7683x; 2.7683x over previous
#include <cuda_runtime.h>
#include <cuda_bf16.h>
#include <math.h>
#include <stdint.h>

// ---------------- problem constants ----------------
#define Bz 32
#define TE 2048
#define TDd 64
#define Dd 1024
#define Mrows (Bz * TE)      // 65536

// ---------------- scratch (device globals) ----------------
__device__ __nv_bfloat16 g_Ahi[(size_t)Mrows * Dd];
__device__ __nv_bfloat16 g_Alo[(size_t)Mrows * Dd];
__device__ __nv_bfloat16 g_Bhi[(size_t)Dd * Dd];      // W^T hi : [n][k]
__device__ __nv_bfloat16 g_Blo[(size_t)Dd * Dd];      // W^T lo : [n][k]
__device__ float g_dU[Bz * Dd];
__device__ float g_scores[Bz * TE];
__device__ float g_weights[Bz * TE];

// ---------------- small helpers ----------------
__device__ __forceinline__ uint32_t smem_to_u32(const void* p) {
    uint32_t a;
    asm("{ .reg .u64 t; cvta.to.shared.u64 t, %1; cvt.u32.u64 %0, t; }" : "=r"(a) : "l"(p));
    return a;
}
__device__ __forceinline__ void cp16(uint32_t s, const void* g) {
    asm volatile("cp.async.cg.shared.global [%0], [%1], 16;" :: "r"(s), "l"(g));
}
#define CP_COMMIT() asm volatile("cp.async.commit_group;" ::: "memory")
#define CP_WAIT(n)  asm volatile("cp.async.wait_group %0;" :: "n"(n) : "memory")
#define LDSM_X4(r0, r1, r2, r3, addr) \
    asm volatile("ldmatrix.sync.aligned.m8n8.x4.shared.b16 {%0,%1,%2,%3}, [%4];" \
        : "=r"(r0), "=r"(r1), "=r"(r2), "=r"(r3) : "r"(addr))
#define MMA16816(d0, d1, d2, d3, a0, a1, a2, a3, b0, b1) \
    asm volatile("mma.sync.aligned.m16n8k16.row.col.f32.bf16.bf16.f32 " \
        "{%0,%1,%2,%3}, {%4,%5,%6,%7}, {%8,%9}, {%0,%1,%2,%3};" \
        : "+f"(d0), "+f"(d1), "+f"(d2), "+f"(d3) \
        : "r"(a0), "r"(a1), "r"(a2), "r"(a3), "r"(b0), "r"(b1))

__device__ __forceinline__ uint32_t sw128(uint32_t off) {
    return off ^ ((off >> 3) & 0x70);
}

// ---------------- GEMM tiling ----------------
#define BM 128
#define BN 128
#define BKE 64                       // bf16 k per chunk (128 B rows)
#define NCHUNK 48                    // 3 split phases * 16
#define A_TILE_B (BM * 128)          // 16384
#define B_TILE_B (BN * 128)          // 16384
#define SMEM_TOTAL (4 * 16384)       // A0,A1,B0,B1

// ---------------- conversion kernels ----------------
__global__ void convert_A_kernel(const float* __restrict__ enc) {
    size_t i = ((size_t)blockIdx.x * blockDim.x + threadIdx.x) * 4;
    float4 v = *(const float4*)(enc + i);
    __nv_bfloat16 h0 = __float2bfloat16(v.x);
    __nv_bfloat16 h1 = __float2bfloat16(v.y);
    __nv_bfloat16 h2 = __float2bfloat16(v.z);
    __nv_bfloat16 h3 = __float2bfloat16(v.w);
    __nv_bfloat162 hi0; hi0.x = h0; hi0.y = h1;
    __nv_bfloat162 hi1; hi1.x = h2; hi1.y = h3;
    *(__nv_bfloat162*)(g_Ahi + i)     = hi0;
    *(__nv_bfloat162*)(g_Ahi + i + 2) = hi1;
    __nv_bfloat162 lo0, lo1;
    lo0.x = __float2bfloat16(v.x - __bfloat162float(h0));
    lo0.y = __float2bfloat16(v.y - __bfloat162float(h1));
    lo1.x = __float2bfloat16(v.z - __bfloat162float(h2));
    lo1.y = __float2bfloat16(v.w - __bfloat162float(h3));
    *(__nv_bfloat162*)(g_Alo + i)     = lo0;
    *(__nv_bfloat162*)(g_Alo + i + 2) = lo1;
}

__global__ void convert_W_kernel(const float* __restrict__ W) {
    int id = blockIdx.x * 256 + threadIdx.x;
    int n = id >> 10, k = id & 1023;
    float v = W[(size_t)k * Dd + n];           // transpose
    __nv_bfloat16 h = __float2bfloat16(v);
    g_Bhi[(size_t)n * Dd + k] = h;
    g_Blo[(size_t)n * Dd + k] = __float2bfloat16(v - __bfloat162float(h));
}

__global__ void zero_scores_kernel() {
    int i = blockIdx.x * blockDim.x + threadIdx.x;
    if (i < Bz * TE) g_scores[i] = 0.0f;
}

__global__ void dU_kernel(const float* __restrict__ dec, const float* __restrict__ U) {
    int b = blockIdx.x;
    int f = blockIdx.y * blockDim.x + threadIdx.x;
    __shared__ float sdec[Dd];
    const float* drow = dec + (size_t)b * TDd * Dd + (size_t)(TDd - 1) * Dd;
    for (int i = threadIdx.x; i < Dd; i += blockDim.x) sdec[i] = drow[i];
    __syncthreads();
    float acc = 0.0f;
#pragma unroll 8
    for (int e = 0; e < Dd; e++) acc = fmaf(sdec[e], U[(size_t)e * Dd + f], acc);
    g_dU[b * Dd + f] = acc;
}

// ---------------- main fused GEMM (HMMA) ----------------
__device__ __forceinline__ void load_chunk(uint32_t sbase, int stage, int c,
                                           int mbase, int nbase, int tid) {
    int phase = c >> 4;
    int kb = (c & 15) * BKE;
    const __nv_bfloat16* Ap = (phase < 2) ? g_Ahi : g_Alo;
    const __nv_bfloat16* Bp = (phase == 1) ? g_Blo : g_Bhi;
    uint32_t sA = sbase + stage * A_TILE_B;
    uint32_t sB = sbase + 2 * A_TILE_B + stage * B_TILE_B;
#pragma unroll
    for (int i = 0; i < 4; i++) {
        int u = tid + i * 256;              // 0..1023
        int r = u >> 3, ch = u & 7;
        cp16(sA + sw128((uint32_t)(r * 128 + ch * 16)),
             Ap + (size_t)(mbase + r) * Dd + kb + ch * 8);
    }
#pragma unroll
    for (int i = 0; i < 4; i++) {
        int u = tid + i * 256;
        int r = u >> 3, ch = u & 7;
        cp16(sB + sw128((uint32_t)(r * 128 + ch * 16)),
             Bp + (size_t)(nbase + r) * Dd + kb + ch * 8);
    }
    CP_COMMIT();
}

__global__ void __launch_bounds__(256, 2) gemm_score_mma(const float* __restrict__ V) {
    extern __shared__ char smem[];
    uint32_t sbase = smem_to_u32(smem);

    const int tid  = threadIdx.x;
    const int wid  = tid >> 5;
    const int lane = tid & 31;
    const int wm   = wid >> 2;      // 0..1  (64 rows each)
    const int wn   = wid & 3;       // 0..3  (32 cols each)

    const int nblk  = blockIdx.x & 7;
    const int mblk  = blockIdx.x >> 3;
    const int mbase = mblk * BM;
    const int nbase = nblk * BN;
    const int b     = mbase >> 11;  // batch index

    float acc[4][4][4];
#pragma unroll
    for (int mt = 0; mt < 4; mt++)
#pragma unroll
        for (int nt = 0; nt < 4; nt++)
#pragma unroll
            for (int i = 0; i < 4; i++) acc[mt][nt][i] = 0.0f;

    // per-lane ldmatrix source geometry
    const int a_r  = lane & 15;            // row within m16 tile
    const int a_kc = lane >> 4;            // 0/1: k 16B-chunk select
    const int b_n  = ((lane >> 4) & 1) * 8 + (lane & 7);  // row within n16 pair
    const int b_kc = (lane >> 3) & 1;

    load_chunk(sbase, 0, 0, mbase, nbase, tid);

    for (int c = 0; c < NCHUNK; c++) {
        if (c > 0) __syncthreads();                 // buffer reuse guard
        if (c + 1 < NCHUNK) {
            load_chunk(sbase, (c + 1) & 1, c + 1, mbase, nbase, tid);
            CP_WAIT(1);
        } else {
            CP_WAIT(0);
        }
        __syncthreads();

        const int stage = c & 1;
        const uint32_t sA = sbase + stage * A_TILE_B;
        const uint32_t sB = sbase + 2 * A_TILE_B + stage * B_TILE_B;

#pragma unroll
        for (int ks = 0; ks < 4; ks++) {
            uint32_t af[4][4];
#pragma unroll
            for (int mt = 0; mt < 4; mt++) {
                int row = wm * 64 + mt * 16 + a_r;
                uint32_t off = (uint32_t)(row * 128 + (ks * 2 + a_kc) * 16);
                LDSM_X4(af[mt][0], af[mt][1], af[mt][2], af[mt][3], sA + sw128(off));
            }
            uint32_t bf[2][4];
#pragma unroll
            for (int p = 0; p < 2; p++) {
                int row = wn * 32 + p * 16 + b_n;
                uint32_t off = (uint32_t)(row * 128 + (ks * 2 + b_kc) * 16);
                LDSM_X4(bf[p][0], bf[p][1], bf[p][2], bf[p][3], sB + sw128(off));
            }
#pragma unroll
            for (int mt = 0; mt < 4; mt++)
#pragma unroll
                for (int nt = 0; nt < 4; nt++) {
                    uint32_t b0 = bf[nt >> 1][(nt & 1) * 2];
                    uint32_t b1 = bf[nt >> 1][(nt & 1) * 2 + 1];
                    MMA16816(acc[mt][nt][0], acc[mt][nt][1], acc[mt][nt][2], acc[mt][nt][3],
                             af[mt][0], af[mt][1], af[mt][2], af[mt][3], b0, b1);
                }
        }
    }

    // ---- fused epilogue: scores[m] += sum_n V[n]*tanh(C[m][n] + dU[b][n]) ----
    const int q = lane >> 2;       // quad id = row within m16 half
    const int t4 = lane & 3;
#pragma unroll
    for (int mt = 0; mt < 4; mt++) {
        float s0 = 0.0f, s1 = 0.0f;
#pragma unroll
        for (int nt = 0; nt < 4; nt++) {
            int n0 = nbase + wn * 32 + nt * 8 + 2 * t4;
            float v0 = V[n0], v1 = V[n0 + 1];
            float u0 = g_dU[b * Dd + n0], u1 = g_dU[b * Dd + n0 + 1];
            s0 = fmaf(v0, tanhf(acc[mt][nt][0] + u0), s0);
            s0 = fmaf(v1, tanhf(acc[mt][nt][1] + u1), s0);
            s1 = fmaf(v0, tanhf(acc[mt][nt][2] + u0), s1);
            s1 = fmaf(v1, tanhf(acc[mt][nt][3] + u1), s1);
        }
        s0 += __shfl_xor_sync(0xFFFFFFFF, s0, 1);
        s0 += __shfl_xor_sync(0xFFFFFFFF, s0, 2);
        s1 += __shfl_xor_sync(0xFFFFFFFF, s1, 1);
        s1 += __shfl_xor_sync(0xFFFFFFFF, s1, 2);
        if (t4 == 0) {
            int row = mbase + wm * 64 + mt * 16 + q;
            atomicAdd(&g_scores[row], s0);
            atomicAdd(&g_scores[row + 8], s1);
        }
    }
}

// ---------------- softmax & context ----------------
__global__ void softmax_kernel(float* __restrict__ out_weights) {
    const int b = blockIdx.x;
    const int tid = threadIdx.x;
    __shared__ float red[256];
    float local[8];
    float mx = -INFINITY;
#pragma unroll
    for (int i = 0; i < 8; i++) {
        local[i] = g_scores[b * TE + tid + i * 256];
        mx = fmaxf(mx, local[i]);
    }
    red[tid] = mx;
    __syncthreads();
    for (int s = 128; s > 0; s >>= 1) {
        if (tid < s) red[tid] = fmaxf(red[tid], red[tid + s]);
        __syncthreads();
    }
    mx = red[0];
    __syncthreads();
    float sum = 0.0f;
#pragma unroll
    for (int i = 0; i < 8; i++) { local[i] = expf(local[i] - mx); sum += local[i]; }
    red[tid] = sum;
    __syncthreads();
    for (int s = 128; s > 0; s >>= 1) {
        if (tid < s) red[tid] += red[tid + s];
        __syncthreads();
    }
    const float inv = 1.0f / red[0];
#pragma unroll
    for (int i = 0; i < 8; i++) {
        float w = local[i] * inv;
        g_weights[b * TE + tid + i * 256]   = w;
        out_weights[b * TE + tid + i * 256] = w;
    }
}

__global__ void context_kernel(const float* __restrict__ enc, float* __restrict__ out_context) {
    const int b = blockIdx.x;
    const int e = blockIdx.y * 256 + threadIdx.x;
    __shared__ float sw[TE];
    for (int i = threadIdx.x; i < TE; i += 256) sw[i] = g_weights[b * TE + i];
    __syncthreads();
    const float* base = enc + (size_t)b * TE * Dd + e;
    float acc = 0.0f;
#pragma unroll 8
    for (int t = 0; t < TE; t++) acc = fmaf(sw[t], base[(size_t)t * Dd], acc);
    out_context[b * Dd + e] = acc;
}

// ---------------- launch ----------------
extern "C" void kernel_launch(void* const* d_in, const int* in_sizes, int n_in,
                              void* d_out, int out_size) {
    const float* enc = (const float*)d_in[0];
    const float* dec = (const float*)d_in[1];
    const float* W_a = (const float*)d_in[2];
    const float* U_a = (const float*)d_in[3];
    const float* V_a = (const float*)d_in[4];
    float* out = (float*)d_out;
    float* out_context = out;            // 32*1024
    float* out_weights = out + Bz * Dd;  // 32*2048

    static int smem_set = 0;
    if (!smem_set) {
        cudaFuncSetAttribute(gemm_score_mma, cudaFuncAttributeMaxDynamicSharedMemorySize, SMEM_TOTAL);
        smem_set = 1;
    }

    convert_A_kernel<<<(Mrows * (Dd / 4)) / 256, 256>>>(enc);
    convert_W_kernel<<<(Dd * Dd) / 256, 256>>>(W_a);
    zero_scores_kernel<<<(Bz * TE + 255) / 256, 256>>>();
    {
        dim3 g(Bz, Dd / 128);
        dU_kernel<<<g, 128>>>(dec, U_a);
    }
    gemm_score_mma<<<(Mrows / BM) * (Dd / BN), 256, SMEM_TOTAL>>>(V_a);
    softmax_kernel<<<Bz, 256>>>(out_weights);
    {
        dim3 g(Bz, Dd / 256);
        context_kernel<<<g, 256>>>(enc, out_context);
    }
}